// round 1
// baseline (speedup 1.0000x reference)
#include <cuda_runtime.h>
#include <cstdint>
#include <cstdio>

#define N_NODES 8192
#define F_IN    512
#define HID     256
#define CLS     16

// Scratch (allocation-free rule: __device__ globals)
__device__ float g_deg[N_NODES];            // 32 KB
__device__ float g_Y1[N_NODES * HID];       // 8 MB: d_j * (X @ W1^T)
__device__ float g_X1[N_NODES * HID];       // 8 MB: relu(d_i * (A @ Y1))
__device__ float g_Y2[N_NODES * CLS];       // 512 KB: d_j * (X1 @ W2^T)

// ---------------------------------------------------------------------------
// helpers
// ---------------------------------------------------------------------------
__device__ __forceinline__ uint32_t f2tf32(float x) {
    uint32_t r;
    asm("cvt.rna.tf32.f32 %0, %1;" : "=r"(r) : "f"(x));
    return r;
}

__device__ __forceinline__ void mma_tf32(float c[4], const uint32_t a[4], const uint32_t b[2]) {
    asm volatile(
        "mma.sync.aligned.m16n8k8.row.col.f32.tf32.tf32.f32 "
        "{%0,%1,%2,%3}, {%4,%5,%6,%7}, {%8,%9}, {%0,%1,%2,%3};"
        : "+f"(c[0]), "+f"(c[1]), "+f"(c[2]), "+f"(c[3])
        : "r"(a[0]), "r"(a[1]), "r"(a[2]), "r"(a[3]),
          "r"(b[0]), "r"(b[1]));
}

// ---------------------------------------------------------------------------
// K1: d[i] = rsqrt(sum_j A[i][j])
// ---------------------------------------------------------------------------
__global__ __launch_bounds__(256) void k_rowsum(const float* __restrict__ A) {
    int row = blockIdx.x;
    const float4* a = reinterpret_cast<const float4*>(A + (size_t)row * N_NODES);
    float s = 0.f;
    #pragma unroll 4
    for (int i = threadIdx.x; i < N_NODES / 4; i += 256) {
        float4 v = a[i];
        s += (v.x + v.y) + (v.z + v.w);
    }
    #pragma unroll
    for (int o = 16; o > 0; o >>= 1) s += __shfl_xor_sync(0xffffffffu, s, o);
    __shared__ float ws[8];
    if ((threadIdx.x & 31) == 0) ws[threadIdx.x >> 5] = s;
    __syncthreads();
    if (threadIdx.x == 0) {
        float v = 0.f;
        #pragma unroll
        for (int i = 0; i < 8; i++) v += ws[i];
        g_deg[row] = rsqrtf(v);
    }
}

// ---------------------------------------------------------------------------
// tf32 tensor-core GEMM: C[m][n] = post( d[m] * sum_k Aop[m][k] * B(k,n) )
//   Aop: [M, Kdim] row-major (lda = Kdim)
//   B_NK = true : Bop is [N, Kdim] row-major (B(k,n) = Bop[n][k])   (X@W1^T case)
//   B_NK = false: Bop is [Kdim, N] row-major (B(k,n) = Bop[k][n])   (A@Y1 case)
// Block tile 128x64x32, 8 warps in 4x2 grid, warp tile 32x32 (m16n8k8 MMAs).
// Smem pads: A stride 36 (== 4 mod 32), B stride 72 (== 8 mod 32) -> frag LDS
// conflict-free.
// ---------------------------------------------------------------------------
template <bool B_NK, bool RELU>
__global__ __launch_bounds__(256, 2)
void k_gemm_tf32(const float* __restrict__ Aop, int lda,
                 const float* __restrict__ Bop, int ldb,
                 float* __restrict__ Cout, int ldc, int Kdim)
{
    __shared__ uint32_t As[128][36];
    __shared__ uint32_t Bs[32][72];

    const int m0 = blockIdx.x * 128, n0 = blockIdx.y * 64;
    const int tid = threadIdx.x, lane = tid & 31, warp = tid >> 5;
    const int wm = (warp >> 1) * 32, wn = (warp & 1) * 32;
    const int g = lane >> 2, t = lane & 3;

    float acc[2][4][4] = {};

    const int nk = Kdim >> 5;
    const int arow = tid >> 3, ac4 = tid & 7;

    float4 pa[4], pb[2];

    // prefetch tile 0
    #pragma unroll
    for (int i = 0; i < 4; i++)
        pa[i] = *reinterpret_cast<const float4*>(
            &Aop[(size_t)(m0 + arow + i * 32) * lda + ac4 * 4]);
    if (B_NK) {
        #pragma unroll
        for (int j = 0; j < 2; j++) {
            int e = tid + j * 256, n = e >> 3, c4 = e & 7;
            pb[j] = *reinterpret_cast<const float4*>(
                &Bop[(size_t)(n0 + n) * ldb + c4 * 4]);
        }
    } else {
        #pragma unroll
        for (int j = 0; j < 2; j++) {
            int e = tid + j * 256, r = e >> 4, c4 = e & 15;
            pb[j] = *reinterpret_cast<const float4*>(
                &Bop[(size_t)r * ldb + n0 + c4 * 4]);
        }
    }

    for (int kt = 0; kt < nk; kt++) {
        // store prefetched tile to smem (with tf32 rounding)
        #pragma unroll
        for (int i = 0; i < 4; i++) {
            int r = arow + i * 32;
            As[r][ac4 * 4 + 0] = f2tf32(pa[i].x);
            As[r][ac4 * 4 + 1] = f2tf32(pa[i].y);
            As[r][ac4 * 4 + 2] = f2tf32(pa[i].z);
            As[r][ac4 * 4 + 3] = f2tf32(pa[i].w);
        }
        if (B_NK) {
            #pragma unroll
            for (int j = 0; j < 2; j++) {
                int e = tid + j * 256, n = e >> 3, c4 = e & 7;
                Bs[c4 * 4 + 0][n] = f2tf32(pb[j].x);
                Bs[c4 * 4 + 1][n] = f2tf32(pb[j].y);
                Bs[c4 * 4 + 2][n] = f2tf32(pb[j].z);
                Bs[c4 * 4 + 3][n] = f2tf32(pb[j].w);
            }
        } else {
            #pragma unroll
            for (int j = 0; j < 2; j++) {
                int e = tid + j * 256, r = e >> 4, c4 = e & 15;
                Bs[r][c4 * 4 + 0] = f2tf32(pb[j].x);
                Bs[r][c4 * 4 + 1] = f2tf32(pb[j].y);
                Bs[r][c4 * 4 + 2] = f2tf32(pb[j].z);
                Bs[r][c4 * 4 + 3] = f2tf32(pb[j].w);
            }
        }
        __syncthreads();

        // prefetch next tile (global loads overlap compute below)
        if (kt + 1 < nk) {
            int koff = (kt + 1) * 32;
            #pragma unroll
            for (int i = 0; i < 4; i++)
                pa[i] = *reinterpret_cast<const float4*>(
                    &Aop[(size_t)(m0 + arow + i * 32) * lda + koff + ac4 * 4]);
            if (B_NK) {
                #pragma unroll
                for (int j = 0; j < 2; j++) {
                    int e = tid + j * 256, n = e >> 3, c4 = e & 7;
                    pb[j] = *reinterpret_cast<const float4*>(
                        &Bop[(size_t)(n0 + n) * ldb + koff + c4 * 4]);
                }
            } else {
                #pragma unroll
                for (int j = 0; j < 2; j++) {
                    int e = tid + j * 256, r = e >> 4, c4 = e & 15;
                    pb[j] = *reinterpret_cast<const float4*>(
                        &Bop[(size_t)(koff + r) * ldb + n0 + c4 * 4]);
                }
            }
        }

        // compute 4 k-steps of 8
        #pragma unroll
        for (int ks = 0; ks < 32; ks += 8) {
            uint32_t af[2][4], bf[4][2];
            #pragma unroll
            for (int mi = 0; mi < 2; mi++) {
                int r = wm + mi * 16 + g;
                af[mi][0] = As[r][ks + t];
                af[mi][1] = As[r + 8][ks + t];
                af[mi][2] = As[r][ks + t + 4];
                af[mi][3] = As[r + 8][ks + t + 4];
            }
            #pragma unroll
            for (int ni = 0; ni < 4; ni++) {
                int c = wn + ni * 8 + g;
                bf[ni][0] = Bs[ks + t][c];
                bf[ni][1] = Bs[ks + t + 4][c];
            }
            #pragma unroll
            for (int mi = 0; mi < 2; mi++)
                #pragma unroll
                for (int ni = 0; ni < 4; ni++)
                    mma_tf32(acc[mi][ni], af[mi], bf[ni]);
        }
        __syncthreads();
    }

    // epilogue: scale by d[m], optional relu
    #pragma unroll
    for (int mi = 0; mi < 2; mi++) {
        int r = m0 + wm + mi * 16 + g;
        float d0 = g_deg[r], d1 = g_deg[r + 8];
        #pragma unroll
        for (int ni = 0; ni < 4; ni++) {
            int c = n0 + wn + ni * 8 + 2 * t;
            float v0 = d0 * acc[mi][ni][0], v1 = d0 * acc[mi][ni][1];
            float v2 = d1 * acc[mi][ni][2], v3 = d1 * acc[mi][ni][3];
            if (RELU) {
                v0 = fmaxf(v0, 0.f); v1 = fmaxf(v1, 0.f);
                v2 = fmaxf(v2, 0.f); v3 = fmaxf(v3, 0.f);
            }
            *reinterpret_cast<float2*>(&Cout[(size_t)r * ldc + c]) = make_float2(v0, v1);
            *reinterpret_cast<float2*>(&Cout[(size_t)(r + 8) * ldc + c]) = make_float2(v2, v3);
        }
    }
}

// ---------------------------------------------------------------------------
// K4: g_Y2[j][c] = d[j] * sum_h g_X1[j][h] * W2[c][h]   (tiny GEMM, fp32)
// Block: 16 rows x 16 classes, 256 threads, X1/W2 tiles staged in smem.
// ---------------------------------------------------------------------------
__global__ __launch_bounds__(256) void k_xw2(const float* __restrict__ W2) {
    __shared__ float xs[16][257];
    __shared__ float ws[16][257];
    const int tid = threadIdx.x;
    const int r0 = blockIdx.x * 16;
    #pragma unroll
    for (int i = 0; i < 4; i++) {
        int e = tid + i * 256;          // float4 index over 16x256
        int r = e >> 6, c4 = e & 63;
        float4 w = *reinterpret_cast<const float4*>(&W2[(size_t)r * HID + c4 * 4]);
        ws[r][c4 * 4 + 0] = w.x; ws[r][c4 * 4 + 1] = w.y;
        ws[r][c4 * 4 + 2] = w.z; ws[r][c4 * 4 + 3] = w.w;
        float4 x = *reinterpret_cast<const float4*>(&g_X1[(size_t)(r0 + r) * HID + c4 * 4]);
        xs[r][c4 * 4 + 0] = x.x; xs[r][c4 * 4 + 1] = x.y;
        xs[r][c4 * 4 + 2] = x.z; xs[r][c4 * 4 + 3] = x.w;
    }
    __syncthreads();
    int r = tid >> 4, c = tid & 15;
    float s = 0.f;
    #pragma unroll 8
    for (int k = 0; k < HID; k++) s = fmaf(xs[r][k], ws[c][k], s);
    g_Y2[(size_t)(r0 + r) * CLS + c] = g_deg[r0 + r] * s;
}

// ---------------------------------------------------------------------------
// K5: out[i][:] = log_softmax( d[i] * (A[i,:] @ g_Y2) )
// Memory-bound on A (256 MB). 64 rows/block, 4 threads per row (4 cols each),
// log-softmax via quad shuffles in the epilogue.
// ---------------------------------------------------------------------------
__global__ __launch_bounds__(256) void k_out(const float* __restrict__ A,
                                             float* __restrict__ out) {
    __shared__ float As[64][65];
    __shared__ float Ys[64][16];
    const int tid = threadIdx.x;
    const int r0 = blockIdx.x * 64;
    const int r = tid >> 2, cq = tid & 3;
    float4 acc = make_float4(0.f, 0.f, 0.f, 0.f);

    for (int kt = 0; kt < N_NODES; kt += 64) {
        #pragma unroll
        for (int i = 0; i < 4; i++) {
            int e = tid + i * 256, row = e >> 4, c4 = e & 15;
            float4 v = *reinterpret_cast<const float4*>(
                &A[(size_t)(r0 + row) * N_NODES + kt + c4 * 4]);
            As[row][c4 * 4 + 0] = v.x; As[row][c4 * 4 + 1] = v.y;
            As[row][c4 * 4 + 2] = v.z; As[row][c4 * 4 + 3] = v.w;
        }
        // Y2 tile rows kt..kt+63 (flat, no pad -> float4 friendly)
        reinterpret_cast<float4*>(&Ys[0][0])[tid] =
            *reinterpret_cast<const float4*>(&g_Y2[(size_t)kt * CLS + tid * 4]);
        __syncthreads();
        #pragma unroll 16
        for (int k = 0; k < 64; k++) {
            float a = As[r][k];
            float4 y = *reinterpret_cast<const float4*>(&Ys[k][cq * 4]);
            acc.x = fmaf(a, y.x, acc.x);
            acc.y = fmaf(a, y.y, acc.y);
            acc.z = fmaf(a, y.z, acc.z);
            acc.w = fmaf(a, y.w, acc.w);
        }
        __syncthreads();
    }

    float di = g_deg[r0 + r];
    acc.x *= di; acc.y *= di; acc.z *= di; acc.w *= di;

    float m = fmaxf(fmaxf(acc.x, acc.y), fmaxf(acc.z, acc.w));
    m = fmaxf(m, __shfl_xor_sync(0xffffffffu, m, 1));
    m = fmaxf(m, __shfl_xor_sync(0xffffffffu, m, 2));
    float s = expf(acc.x - m) + expf(acc.y - m) + expf(acc.z - m) + expf(acc.w - m);
    s += __shfl_xor_sync(0xffffffffu, s, 1);
    s += __shfl_xor_sync(0xffffffffu, s, 2);
    float ls = logf(s) + m;

    float4 o = make_float4(acc.x - ls, acc.y - ls, acc.z - ls, acc.w - ls);
    *reinterpret_cast<float4*>(&out[(size_t)(r0 + r) * CLS + cq * 4]) = o;
}

// ---------------------------------------------------------------------------
// launch
// ---------------------------------------------------------------------------
extern "C" void kernel_launch(void* const* d_in, const int* in_sizes, int n_in,
                              void* d_out, int out_size) {
    const float* X  = (const float*)d_in[0];   // [8192, 512]
    const float* A  = (const float*)d_in[1];   // [8192, 8192]
    const float* W1 = (const float*)d_in[2];   // [256, 512]
    const float* W2 = (const float*)d_in[3];   // [16, 256]
    float* out = (float*)d_out;                // [8192, 16]

    float *pY1 = nullptr, *pX1 = nullptr;
    cudaGetSymbolAddress((void**)&pY1, g_Y1);
    cudaGetSymbolAddress((void**)&pX1, g_X1);

    // K1: degree scaling vector
    k_rowsum<<<N_NODES, 256>>>(A);

    // K2: Y1 = d ⊙ (X @ W1^T)      [8192 x 256], K = 512
    k_gemm_tf32<true, false><<<dim3(N_NODES / 128, HID / 64), 256>>>(
        X, F_IN, W1, F_IN, pY1, HID, F_IN);

    // K3: X1 = relu(d ⊙ (A @ Y1))  [8192 x 256], K = 8192
    k_gemm_tf32<false, true><<<dim3(N_NODES / 128, HID / 64), 256>>>(
        A, N_NODES, pY1, HID, pX1, HID, N_NODES);

    // K4: Y2 = d ⊙ (X1 @ W2^T)     [8192 x 16]
    k_xw2<<<N_NODES / 16, 256>>>(W2);

    // K5: out = log_softmax(d ⊙ (A @ Y2))
    k_out<<<N_NODES / 64, 256>>>(A, out);
}

// round 2
// speedup vs baseline: 1.1319x; 1.1319x over previous
#include <cuda_runtime.h>
#include <cstdint>
#include <cstdio>

#define N_NODES 8192
#define F_IN    512
#define HID     256
#define CLS     16

// Scratch (allocation-free rule: __device__ globals)
__device__ float g_deg[N_NODES];            // 32 KB
__device__ float g_Y1[N_NODES * HID];       // 8 MB: d_j * (X @ W1^T)
__device__ float g_Y2[N_NODES * CLS];       // 512 KB: d_j * (relu(...) @ W2^T)

// ---------------------------------------------------------------------------
// helpers
// ---------------------------------------------------------------------------
__device__ __forceinline__ uint32_t f2tf32(float x) {
    uint32_t r;
    asm("cvt.rna.tf32.f32 %0, %1;" : "=r"(r) : "f"(x));
    return r;
}

__device__ __forceinline__ void mma_tf32(float c[4], const uint32_t a[4], const uint32_t b[2]) {
    asm volatile(
        "mma.sync.aligned.m16n8k8.row.col.f32.tf32.tf32.f32 "
        "{%0,%1,%2,%3}, {%4,%5,%6,%7}, {%8,%9}, {%0,%1,%2,%3};"
        : "+f"(c[0]), "+f"(c[1]), "+f"(c[2]), "+f"(c[3])
        : "r"(a[0]), "r"(a[1]), "r"(a[2]), "r"(a[3]),
          "r"(b[0]), "r"(b[1]));
}

__device__ __forceinline__ void cp16(void* dst, const void* src) {
    uint32_t d = (uint32_t)__cvta_generic_to_shared(dst);
    asm volatile("cp.async.cg.shared.global [%0], [%1], 16;\n" :: "r"(d), "l"(src));
}
__device__ __forceinline__ void cp_commit() {
    asm volatile("cp.async.commit_group;\n" ::: "memory");
}
template <int Nn>
__device__ __forceinline__ void cp_wait() {
    asm volatile("cp.async.wait_group %0;\n" :: "n"(Nn) : "memory");
}

// ---------------------------------------------------------------------------
// K1: d[i] = rsqrt(sum_j A[i][j])
// ---------------------------------------------------------------------------
__global__ __launch_bounds__(256) void k_rowsum(const float* __restrict__ A) {
    int row = blockIdx.x;
    const float4* a = reinterpret_cast<const float4*>(A + (size_t)row * N_NODES);
    float s = 0.f;
    #pragma unroll 4
    for (int i = threadIdx.x; i < N_NODES / 4; i += 256) {
        float4 v = a[i];
        s += (v.x + v.y) + (v.z + v.w);
    }
    #pragma unroll
    for (int o = 16; o > 0; o >>= 1) s += __shfl_xor_sync(0xffffffffu, s, o);
    __shared__ float ws[8];
    if ((threadIdx.x & 31) == 0) ws[threadIdx.x >> 5] = s;
    __syncthreads();
    if (threadIdx.x == 0) {
        float v = 0.f;
        #pragma unroll
        for (int i = 0; i < 8; i++) v += ws[i];
        g_deg[row] = rsqrtf(v);
    }
}

// ---------------------------------------------------------------------------
// K2: Y1[m][n] = d[m] * sum_k X[m][k] * W1[n][k]   (tf32 MMA, small GEMM)
// Block tile 128x64x32, 8 warps in 4x2, warp tile 32x32.
// ---------------------------------------------------------------------------
__global__ __launch_bounds__(256, 2)
void k_gemm_xw1(const float* __restrict__ Xin,
                const float* __restrict__ W1,
                float* __restrict__ Cout)
{
    __shared__ uint32_t As[128][36];
    __shared__ uint32_t Bs[32][72];

    const int m0 = blockIdx.x * 128, n0 = blockIdx.y * 64;
    const int tid = threadIdx.x, lane = tid & 31, warp = tid >> 5;
    const int wm = (warp >> 1) * 32, wn = (warp & 1) * 32;
    const int g = lane >> 2, t = lane & 3;

    float acc[2][4][4] = {};

    const int nk = F_IN >> 5;
    const int arow = tid >> 3, ac4 = tid & 7;

    float4 pa[4], pb[2];

    #pragma unroll
    for (int i = 0; i < 4; i++)
        pa[i] = *reinterpret_cast<const float4*>(
            &Xin[(size_t)(m0 + arow + i * 32) * F_IN + ac4 * 4]);
    #pragma unroll
    for (int j = 0; j < 2; j++) {
        int e = tid + j * 256, n = e >> 3, c4 = e & 7;
        pb[j] = *reinterpret_cast<const float4*>(
            &W1[(size_t)(n0 + n) * F_IN + c4 * 4]);
    }

    for (int kt = 0; kt < nk; kt++) {
        #pragma unroll
        for (int i = 0; i < 4; i++) {
            int r = arow + i * 32;
            As[r][ac4 * 4 + 0] = f2tf32(pa[i].x);
            As[r][ac4 * 4 + 1] = f2tf32(pa[i].y);
            As[r][ac4 * 4 + 2] = f2tf32(pa[i].z);
            As[r][ac4 * 4 + 3] = f2tf32(pa[i].w);
        }
        #pragma unroll
        for (int j = 0; j < 2; j++) {
            int e = tid + j * 256, n = e >> 3, c4 = e & 7;
            Bs[c4 * 4 + 0][n] = f2tf32(pb[j].x);
            Bs[c4 * 4 + 1][n] = f2tf32(pb[j].y);
            Bs[c4 * 4 + 2][n] = f2tf32(pb[j].z);
            Bs[c4 * 4 + 3][n] = f2tf32(pb[j].w);
        }
        __syncthreads();

        if (kt + 1 < nk) {
            int koff = (kt + 1) * 32;
            #pragma unroll
            for (int i = 0; i < 4; i++)
                pa[i] = *reinterpret_cast<const float4*>(
                    &Xin[(size_t)(m0 + arow + i * 32) * F_IN + koff + ac4 * 4]);
            #pragma unroll
            for (int j = 0; j < 2; j++) {
                int e = tid + j * 256, n = e >> 3, c4 = e & 7;
                pb[j] = *reinterpret_cast<const float4*>(
                    &W1[(size_t)(n0 + n) * F_IN + koff + c4 * 4]);
            }
        }

        #pragma unroll
        for (int ks = 0; ks < 32; ks += 8) {
            uint32_t af[2][4], bf[4][2];
            #pragma unroll
            for (int mi = 0; mi < 2; mi++) {
                int r = wm + mi * 16 + g;
                af[mi][0] = As[r][ks + t];
                af[mi][1] = As[r + 8][ks + t];
                af[mi][2] = As[r][ks + t + 4];
                af[mi][3] = As[r + 8][ks + t + 4];
            }
            #pragma unroll
            for (int ni = 0; ni < 4; ni++) {
                int c = wn + ni * 8 + g;
                bf[ni][0] = Bs[ks + t][c];
                bf[ni][1] = Bs[ks + t + 4][c];
            }
            #pragma unroll
            for (int mi = 0; mi < 2; mi++)
                #pragma unroll
                for (int ni = 0; ni < 4; ni++)
                    mma_tf32(acc[mi][ni], af[mi], bf[ni]);
        }
        __syncthreads();
    }

    #pragma unroll
    for (int mi = 0; mi < 2; mi++) {
        int r = m0 + wm + mi * 16 + g;
        float d0 = g_deg[r], d1 = g_deg[r + 8];
        #pragma unroll
        for (int ni = 0; ni < 4; ni++) {
            int c = n0 + wn + ni * 8 + 2 * t;
            float2 v01 = make_float2(d0 * acc[mi][ni][0], d0 * acc[mi][ni][1]);
            float2 v23 = make_float2(d1 * acc[mi][ni][2], d1 * acc[mi][ni][3]);
            *reinterpret_cast<float2*>(&Cout[(size_t)r * HID + c]) = v01;
            *reinterpret_cast<float2*>(&Cout[(size_t)(r + 8) * HID + c]) = v23;
        }
    }
}

// ---------------------------------------------------------------------------
// K3 (fused): for 64 rows per block over full HID:
//   X1[r][:] = relu(d[r] * (A[r,:] @ Y1))            (tf32 MMA, K = 8192)
//   Y2[r][c] = d[r] * sum_h X1[r][h] * W2[c][h]      (fused epilogue)
// Block tile 64x256x32, 256 threads, 8 warps (2x4), warp tile 32x64.
// cp.async double-buffered; A read from HBM exactly once; Y1 from L2.
// Raw fp32 bits fed as tf32 (HW truncation) -> no cvt needed.
// ---------------------------------------------------------------------------
#define L1_AS_STRIDE 36
#define L1_BS_STRIDE 264
#define L1_AS_BYTES (64 * L1_AS_STRIDE * 4)          // 9216
#define L1_BS_BYTES (32 * L1_BS_STRIDE * 4)          // 33792
#define L1_SMEM_BYTES (2 * (L1_AS_BYTES + L1_BS_BYTES))  // 86016
#define L1_XS_STRIDE 260
#define L1_W2_STRIDE 264

__global__ __launch_bounds__(256, 1)
void k_layer1_fused(const float* __restrict__ A,
                    const float* __restrict__ Y1,
                    const float* __restrict__ W2,
                    float* __restrict__ Y2out)
{
    extern __shared__ char smem[];
    uint32_t (*As)[64][L1_AS_STRIDE] =
        reinterpret_cast<uint32_t (*)[64][L1_AS_STRIDE]>(smem);
    uint32_t (*Bs)[32][L1_BS_STRIDE] =
        reinterpret_cast<uint32_t (*)[32][L1_BS_STRIDE]>(smem + 2 * L1_AS_BYTES);

    const int m0 = blockIdx.x * 64;
    const int tid = threadIdx.x, lane = tid & 31, warp = tid >> 5;
    const int wm = (warp >> 2) * 32;     // 0 or 32
    const int wn = (warp & 3) * 64;      // 0,64,128,192
    const int g = lane >> 2, t = lane & 3;

    float acc[2][8][4] = {};

    // cp.async tile loaders -------------------------------------------------
    // A tile: 64 rows x 32 cols -> 512 x 16B chunks, 2 per thread
    const int a_row = tid >> 3, a_c4 = tid & 7;        // chunk 0: rows 0..31
    // B tile: 32 rows x 256 cols -> 2048 chunks, 8 per thread
    const int b_row = tid >> 6, b_c4 = tid & 63;       // chunk 0: rows 0..3

    auto issue_tile = [&](int kt, int buf) {
        const float* asrc = A + (size_t)(m0 + a_row) * N_NODES + kt * 32 + a_c4 * 4;
        cp16(&(*(As + buf))[a_row][a_c4 * 4], asrc);
        cp16(&(*(As + buf))[a_row + 32][a_c4 * 4], asrc + (size_t)32 * N_NODES);
        const float* bsrc = Y1 + (size_t)(kt * 32 + b_row) * HID + b_c4 * 4;
        #pragma unroll
        for (int j = 0; j < 8; j++)
            cp16(&(*(Bs + buf))[b_row + j * 4][b_c4 * 4], bsrc + (size_t)j * 4 * HID);
    };

    const int nk = N_NODES / 32;   // 256
    issue_tile(0, 0);
    cp_commit();

    for (int kt = 0; kt < nk; kt++) {
        const int buf = kt & 1;
        if (kt + 1 < nk) {
            issue_tile(kt + 1, buf ^ 1);
            cp_commit();
            cp_wait<1>();
        } else {
            cp_wait<0>();
        }
        __syncthreads();

        #pragma unroll
        for (int ks = 0; ks < 32; ks += 8) {
            uint32_t af[2][4], bf[8][2];
            #pragma unroll
            for (int mi = 0; mi < 2; mi++) {
                int r = wm + mi * 16 + g;
                af[mi][0] = (*(As + buf))[r][ks + t];
                af[mi][1] = (*(As + buf))[r + 8][ks + t];
                af[mi][2] = (*(As + buf))[r][ks + t + 4];
                af[mi][3] = (*(As + buf))[r + 8][ks + t + 4];
            }
            #pragma unroll
            for (int ni = 0; ni < 8; ni++) {
                int c = wn + ni * 8 + g;
                bf[ni][0] = (*(Bs + buf))[ks + t][c];
                bf[ni][1] = (*(Bs + buf))[ks + t + 4][c];
            }
            #pragma unroll
            for (int mi = 0; mi < 2; mi++)
                #pragma unroll
                for (int ni = 0; ni < 8; ni++)
                    mma_tf32(acc[mi][ni], af[mi], bf[ni]);
        }
        __syncthreads();
    }

    // ---- fused epilogue: X1 = relu(d*acc) -> smem; Y2 = d*(X1 @ W2^T) ----
    float (*Xs)[L1_XS_STRIDE] = reinterpret_cast<float (*)[L1_XS_STRIDE]>(smem);
    float (*W2s)[L1_W2_STRIDE] =
        reinterpret_cast<float (*)[L1_W2_STRIDE]>(smem + 64 * L1_XS_STRIDE * 4);

    #pragma unroll
    for (int mi = 0; mi < 2; mi++) {
        int r = wm + mi * 16 + g;
        float d0 = g_deg[m0 + r], d1 = g_deg[m0 + r + 8];
        #pragma unroll
        for (int ni = 0; ni < 8; ni++) {
            int c = wn + ni * 8 + 2 * t;
            Xs[r][c]     = fmaxf(d0 * acc[mi][ni][0], 0.f);
            Xs[r][c + 1] = fmaxf(d0 * acc[mi][ni][1], 0.f);
            Xs[r + 8][c]     = fmaxf(d1 * acc[mi][ni][2], 0.f);
            Xs[r + 8][c + 1] = fmaxf(d1 * acc[mi][ni][3], 0.f);
        }
    }
    // load W2 (16 x 256) cooperatively
    #pragma unroll
    for (int i = 0; i < 4; i++) {
        int e = tid + i * 256, r = e >> 6, c4 = e & 63;
        float4 w = *reinterpret_cast<const float4*>(&W2[(size_t)r * HID + c4 * 4]);
        W2s[r][c4 * 4 + 0] = w.x; W2s[r][c4 * 4 + 1] = w.y;
        W2s[r][c4 * 4 + 2] = w.z; W2s[r][c4 * 4 + 3] = w.w;
    }
    __syncthreads();

    {
        const int row = tid >> 2;          // 0..63
        const int cg  = (tid & 3) * 4;     // class group: 4 classes per thread
        float s[4] = {0.f, 0.f, 0.f, 0.f};
        #pragma unroll 4
        for (int k = 0; k < HID; k += 4) {
            float4 xv = *reinterpret_cast<float4*>(&Xs[row][k]);
            #pragma unroll
            for (int i = 0; i < 4; i++) {
                float4 wv = *reinterpret_cast<float4*>(&W2s[cg + i][k]);
                s[i] += xv.x * wv.x + xv.y * wv.y + xv.z * wv.z + xv.w * wv.w;
            }
        }
        float dr = g_deg[m0 + row];
        float4 o = make_float4(dr * s[0], dr * s[1], dr * s[2], dr * s[3]);
        *reinterpret_cast<float4*>(&Y2out[(size_t)(m0 + row) * CLS + cg]) = o;
    }
}

// ---------------------------------------------------------------------------
// K5: out[i][:] = log_softmax( d[i] * (A[i,:] @ g_Y2) )
// ---------------------------------------------------------------------------
__global__ __launch_bounds__(256) void k_out(const float* __restrict__ A,
                                             float* __restrict__ out) {
    __shared__ float As[64][65];
    __shared__ float Ys[64][16];
    const int tid = threadIdx.x;
    const int r0 = blockIdx.x * 64;
    const int r = tid >> 2, cq = tid & 3;
    float4 acc = make_float4(0.f, 0.f, 0.f, 0.f);

    for (int kt = 0; kt < N_NODES; kt += 64) {
        #pragma unroll
        for (int i = 0; i < 4; i++) {
            int e = tid + i * 256, row = e >> 4, c4 = e & 15;
            float4 v = *reinterpret_cast<const float4*>(
                &A[(size_t)(r0 + row) * N_NODES + kt + c4 * 4]);
            As[row][c4 * 4 + 0] = v.x; As[row][c4 * 4 + 1] = v.y;
            As[row][c4 * 4 + 2] = v.z; As[row][c4 * 4 + 3] = v.w;
        }
        reinterpret_cast<float4*>(&Ys[0][0])[tid] =
            *reinterpret_cast<const float4*>(&g_Y2[(size_t)kt * CLS + tid * 4]);
        __syncthreads();
        #pragma unroll 16
        for (int k = 0; k < 64; k++) {
            float a = As[r][k];
            float4 y = *reinterpret_cast<const float4*>(&Ys[k][cq * 4]);
            acc.x = fmaf(a, y.x, acc.x);
            acc.y = fmaf(a, y.y, acc.y);
            acc.z = fmaf(a, y.z, acc.z);
            acc.w = fmaf(a, y.w, acc.w);
        }
        __syncthreads();
    }

    float di = g_deg[r0 + r];
    acc.x *= di; acc.y *= di; acc.z *= di; acc.w *= di;

    float m = fmaxf(fmaxf(acc.x, acc.y), fmaxf(acc.z, acc.w));
    m = fmaxf(m, __shfl_xor_sync(0xffffffffu, m, 1));
    m = fmaxf(m, __shfl_xor_sync(0xffffffffu, m, 2));
    float s = expf(acc.x - m) + expf(acc.y - m) + expf(acc.z - m) + expf(acc.w - m);
    s += __shfl_xor_sync(0xffffffffu, s, 1);
    s += __shfl_xor_sync(0xffffffffu, s, 2);
    float ls = logf(s) + m;

    float4 o = make_float4(acc.x - ls, acc.y - ls, acc.z - ls, acc.w - ls);
    *reinterpret_cast<float4*>(&out[(size_t)(r0 + r) * CLS + cq * 4]) = o;
}

// ---------------------------------------------------------------------------
// launch
// ---------------------------------------------------------------------------
extern "C" void kernel_launch(void* const* d_in, const int* in_sizes, int n_in,
                              void* d_out, int out_size) {
    const float* X  = (const float*)d_in[0];   // [8192, 512]
    const float* A  = (const float*)d_in[1];   // [8192, 8192]
    const float* W1 = (const float*)d_in[2];   // [256, 512]
    const float* W2 = (const float*)d_in[3];   // [16, 256]
    float* out = (float*)d_out;                // [8192, 16]

    float *pY1 = nullptr, *pY2 = nullptr;
    cudaGetSymbolAddress((void**)&pY1, g_Y1);
    cudaGetSymbolAddress((void**)&pY2, g_Y2);

    cudaFuncSetAttribute(k_layer1_fused,
                         cudaFuncAttributeMaxDynamicSharedMemorySize,
                         L1_SMEM_BYTES);

    // K1: degree scaling vector
    k_rowsum<<<N_NODES, 256>>>(A);

    // K2: Y1 = d ⊙ (X @ W1^T)      [8192 x 256], K = 512
    k_gemm_xw1<<<dim3(N_NODES / 128, HID / 64), 256>>>(X, W1, pY1);

    // K3+K4 fused: Y2 = d ⊙ (relu(d ⊙ (A @ Y1)) @ W2^T)
    k_layer1_fused<<<N_NODES / 64, 256, L1_SMEM_BYTES>>>(A, pY1, W2, pY2);

    // K5: out = log_softmax(d ⊙ (A @ Y2))
    k_out<<<N_NODES / 64, 256>>>(A, out);
}

// round 3
// speedup vs baseline: 1.8228x; 1.6104x over previous
#include <cuda_runtime.h>
#include <cstdint>
#include <cstdio>

#define N_NODES 8192
#define F_IN    512
#define HID     256
#define CLS     16

// Scratch (allocation-free rule: __device__ globals)
__device__ float g_deg[N_NODES];            // 32 KB
__device__ float g_Y1[N_NODES * HID];       // 8 MB: d_j * (X @ W1^T)
__device__ float g_Y2[N_NODES * CLS];       // 512 KB: d_j * (relu(...) @ W2^T)

// ---------------------------------------------------------------------------
// helpers
// ---------------------------------------------------------------------------
__device__ __forceinline__ uint32_t f2tf32(float x) {
    uint32_t r;
    asm("cvt.rna.tf32.f32 %0, %1;" : "=r"(r) : "f"(x));
    return r;
}

__device__ __forceinline__ void mma_tf32(float c[4], const uint32_t a[4], const uint32_t b[2]) {
    asm volatile(
        "mma.sync.aligned.m16n8k8.row.col.f32.tf32.tf32.f32 "
        "{%0,%1,%2,%3}, {%4,%5,%6,%7}, {%8,%9}, {%0,%1,%2,%3};"
        : "+f"(c[0]), "+f"(c[1]), "+f"(c[2]), "+f"(c[3])
        : "r"(a[0]), "r"(a[1]), "r"(a[2]), "r"(a[3]),
          "r"(b[0]), "r"(b[1]));
}

__device__ __forceinline__ void cp16(void* dst, const void* src) {
    uint32_t d = (uint32_t)__cvta_generic_to_shared(dst);
    asm volatile("cp.async.cg.shared.global [%0], [%1], 16;\n" :: "r"(d), "l"(src));
}
__device__ __forceinline__ void cp_commit() {
    asm volatile("cp.async.commit_group;\n" ::: "memory");
}
template <int Nn>
__device__ __forceinline__ void cp_wait() {
    asm volatile("cp.async.wait_group %0;\n" :: "n"(Nn) : "memory");
}

// ---------------------------------------------------------------------------
// K1: d[i] = rsqrt(sum_j A[i][j])
// ---------------------------------------------------------------------------
__global__ __launch_bounds__(256) void k_rowsum(const float* __restrict__ A) {
    int row = blockIdx.x;
    const float4* a = reinterpret_cast<const float4*>(A + (size_t)row * N_NODES);
    float s = 0.f;
    #pragma unroll 4
    for (int i = threadIdx.x; i < N_NODES / 4; i += 256) {
        float4 v = a[i];
        s += (v.x + v.y) + (v.z + v.w);
    }
    #pragma unroll
    for (int o = 16; o > 0; o >>= 1) s += __shfl_xor_sync(0xffffffffu, s, o);
    __shared__ float ws[8];
    if ((threadIdx.x & 31) == 0) ws[threadIdx.x >> 5] = s;
    __syncthreads();
    if (threadIdx.x == 0) {
        float v = 0.f;
        #pragma unroll
        for (int i = 0; i < 8; i++) v += ws[i];
        g_deg[row] = rsqrtf(v);
    }
}

// ---------------------------------------------------------------------------
// K2: Y1[m][n] = d[m] * sum_k X[m][k] * W1[n][k]   (tf32 MMA, small GEMM)
// ---------------------------------------------------------------------------
__global__ __launch_bounds__(256, 2)
void k_gemm_xw1(const float* __restrict__ Xin,
                const float* __restrict__ W1,
                float* __restrict__ Cout)
{
    __shared__ uint32_t As[128][36];
    __shared__ uint32_t Bs[32][72];

    const int m0 = blockIdx.x * 128, n0 = blockIdx.y * 64;
    const int tid = threadIdx.x, lane = tid & 31, warp = tid >> 5;
    const int wm = (warp >> 1) * 32, wn = (warp & 1) * 32;
    const int g = lane >> 2, t = lane & 3;

    float acc[2][4][4] = {};

    const int nk = F_IN >> 5;
    const int arow = tid >> 3, ac4 = tid & 7;

    float4 pa[4], pb[2];

    #pragma unroll
    for (int i = 0; i < 4; i++)
        pa[i] = *reinterpret_cast<const float4*>(
            &Xin[(size_t)(m0 + arow + i * 32) * F_IN + ac4 * 4]);
    #pragma unroll
    for (int j = 0; j < 2; j++) {
        int e = tid + j * 256, n = e >> 3, c4 = e & 7;
        pb[j] = *reinterpret_cast<const float4*>(
            &W1[(size_t)(n0 + n) * F_IN + c4 * 4]);
    }

    for (int kt = 0; kt < nk; kt++) {
        #pragma unroll
        for (int i = 0; i < 4; i++) {
            int r = arow + i * 32;
            As[r][ac4 * 4 + 0] = f2tf32(pa[i].x);
            As[r][ac4 * 4 + 1] = f2tf32(pa[i].y);
            As[r][ac4 * 4 + 2] = f2tf32(pa[i].z);
            As[r][ac4 * 4 + 3] = f2tf32(pa[i].w);
        }
        #pragma unroll
        for (int j = 0; j < 2; j++) {
            int e = tid + j * 256, n = e >> 3, c4 = e & 7;
            Bs[c4 * 4 + 0][n] = f2tf32(pb[j].x);
            Bs[c4 * 4 + 1][n] = f2tf32(pb[j].y);
            Bs[c4 * 4 + 2][n] = f2tf32(pb[j].z);
            Bs[c4 * 4 + 3][n] = f2tf32(pb[j].w);
        }
        __syncthreads();

        if (kt + 1 < nk) {
            int koff = (kt + 1) * 32;
            #pragma unroll
            for (int i = 0; i < 4; i++)
                pa[i] = *reinterpret_cast<const float4*>(
                    &Xin[(size_t)(m0 + arow + i * 32) * F_IN + koff + ac4 * 4]);
            #pragma unroll
            for (int j = 0; j < 2; j++) {
                int e = tid + j * 256, n = e >> 3, c4 = e & 7;
                pb[j] = *reinterpret_cast<const float4*>(
                    &W1[(size_t)(n0 + n) * F_IN + koff + c4 * 4]);
            }
        }

        #pragma unroll
        for (int ks = 0; ks < 32; ks += 8) {
            uint32_t af[2][4], bf[4][2];
            #pragma unroll
            for (int mi = 0; mi < 2; mi++) {
                int r = wm + mi * 16 + g;
                af[mi][0] = As[r][ks + t];
                af[mi][1] = As[r + 8][ks + t];
                af[mi][2] = As[r][ks + t + 4];
                af[mi][3] = As[r + 8][ks + t + 4];
            }
            #pragma unroll
            for (int ni = 0; ni < 4; ni++) {
                int c = wn + ni * 8 + g;
                bf[ni][0] = Bs[ks + t][c];
                bf[ni][1] = Bs[ks + t + 4][c];
            }
            #pragma unroll
            for (int mi = 0; mi < 2; mi++)
                #pragma unroll
                for (int ni = 0; ni < 4; ni++)
                    mma_tf32(acc[mi][ni], af[mi], bf[ni]);
        }
        __syncthreads();
    }

    #pragma unroll
    for (int mi = 0; mi < 2; mi++) {
        int r = m0 + wm + mi * 16 + g;
        float d0 = g_deg[r], d1 = g_deg[r + 8];
        #pragma unroll
        for (int ni = 0; ni < 4; ni++) {
            int c = n0 + wn + ni * 8 + 2 * t;
            float2 v01 = make_float2(d0 * acc[mi][ni][0], d0 * acc[mi][ni][1]);
            float2 v23 = make_float2(d1 * acc[mi][ni][2], d1 * acc[mi][ni][3]);
            *reinterpret_cast<float2*>(&Cout[(size_t)r * HID + c]) = v01;
            *reinterpret_cast<float2*>(&Cout[(size_t)(r + 8) * HID + c]) = v23;
        }
    }
}

// ---------------------------------------------------------------------------
// K3 (fused): X1 = relu(d ⊙ (A @ Y1)); Y2 = d ⊙ (X1 @ W2^T)
// Block tile 64x256x32, cp.async double-buffered, raw-bit tf32.
// ---------------------------------------------------------------------------
#define L1_AS_STRIDE 36
#define L1_BS_STRIDE 264
#define L1_AS_BYTES (64 * L1_AS_STRIDE * 4)
#define L1_BS_BYTES (32 * L1_BS_STRIDE * 4)
#define L1_SMEM_BYTES (2 * (L1_AS_BYTES + L1_BS_BYTES))
#define L1_XS_STRIDE 260
#define L1_W2_STRIDE 264

__global__ __launch_bounds__(256, 1)
void k_layer1_fused(const float* __restrict__ A,
                    const float* __restrict__ Y1,
                    const float* __restrict__ W2,
                    float* __restrict__ Y2out)
{
    extern __shared__ char smem[];
    uint32_t (*As)[64][L1_AS_STRIDE] =
        reinterpret_cast<uint32_t (*)[64][L1_AS_STRIDE]>(smem);
    uint32_t (*Bs)[32][L1_BS_STRIDE] =
        reinterpret_cast<uint32_t (*)[32][L1_BS_STRIDE]>(smem + 2 * L1_AS_BYTES);

    const int m0 = blockIdx.x * 64;
    const int tid = threadIdx.x, lane = tid & 31, warp = tid >> 5;
    const int wm = (warp >> 2) * 32;
    const int wn = (warp & 3) * 64;
    const int g = lane >> 2, t = lane & 3;

    float acc[2][8][4] = {};

    const int a_row = tid >> 3, a_c4 = tid & 7;
    const int b_row = tid >> 6, b_c4 = tid & 63;

    auto issue_tile = [&](int kt, int buf) {
        const float* asrc = A + (size_t)(m0 + a_row) * N_NODES + kt * 32 + a_c4 * 4;
        cp16(&(*(As + buf))[a_row][a_c4 * 4], asrc);
        cp16(&(*(As + buf))[a_row + 32][a_c4 * 4], asrc + (size_t)32 * N_NODES);
        const float* bsrc = Y1 + (size_t)(kt * 32 + b_row) * HID + b_c4 * 4;
        #pragma unroll
        for (int j = 0; j < 8; j++)
            cp16(&(*(Bs + buf))[b_row + j * 4][b_c4 * 4], bsrc + (size_t)j * 4 * HID);
    };

    const int nk = N_NODES / 32;
    issue_tile(0, 0);
    cp_commit();

    for (int kt = 0; kt < nk; kt++) {
        const int buf = kt & 1;
        if (kt + 1 < nk) {
            issue_tile(kt + 1, buf ^ 1);
            cp_commit();
            cp_wait<1>();
        } else {
            cp_wait<0>();
        }
        __syncthreads();

        #pragma unroll
        for (int ks = 0; ks < 32; ks += 8) {
            uint32_t af[2][4], bf[8][2];
            #pragma unroll
            for (int mi = 0; mi < 2; mi++) {
                int r = wm + mi * 16 + g;
                af[mi][0] = (*(As + buf))[r][ks + t];
                af[mi][1] = (*(As + buf))[r + 8][ks + t];
                af[mi][2] = (*(As + buf))[r][ks + t + 4];
                af[mi][3] = (*(As + buf))[r + 8][ks + t + 4];
            }
            #pragma unroll
            for (int ni = 0; ni < 8; ni++) {
                int c = wn + ni * 8 + g;
                bf[ni][0] = (*(Bs + buf))[ks + t][c];
                bf[ni][1] = (*(Bs + buf))[ks + t + 4][c];
            }
            #pragma unroll
            for (int mi = 0; mi < 2; mi++)
                #pragma unroll
                for (int ni = 0; ni < 8; ni++)
                    mma_tf32(acc[mi][ni], af[mi], bf[ni]);
        }
        __syncthreads();
    }

    float (*Xs)[L1_XS_STRIDE] = reinterpret_cast<float (*)[L1_XS_STRIDE]>(smem);
    float (*W2s)[L1_W2_STRIDE] =
        reinterpret_cast<float (*)[L1_W2_STRIDE]>(smem + 64 * L1_XS_STRIDE * 4);

    #pragma unroll
    for (int mi = 0; mi < 2; mi++) {
        int r = wm + mi * 16 + g;
        float d0 = g_deg[m0 + r], d1 = g_deg[m0 + r + 8];
        #pragma unroll
        for (int ni = 0; ni < 8; ni++) {
            int c = wn + ni * 8 + 2 * t;
            Xs[r][c]     = fmaxf(d0 * acc[mi][ni][0], 0.f);
            Xs[r][c + 1] = fmaxf(d0 * acc[mi][ni][1], 0.f);
            Xs[r + 8][c]     = fmaxf(d1 * acc[mi][ni][2], 0.f);
            Xs[r + 8][c + 1] = fmaxf(d1 * acc[mi][ni][3], 0.f);
        }
    }
    #pragma unroll
    for (int i = 0; i < 4; i++) {
        int e = tid + i * 256, r = e >> 6, c4 = e & 63;
        float4 w = *reinterpret_cast<const float4*>(&W2[(size_t)r * HID + c4 * 4]);
        W2s[r][c4 * 4 + 0] = w.x; W2s[r][c4 * 4 + 1] = w.y;
        W2s[r][c4 * 4 + 2] = w.z; W2s[r][c4 * 4 + 3] = w.w;
    }
    __syncthreads();

    {
        const int row = tid >> 2;
        const int cg  = (tid & 3) * 4;
        float s[4] = {0.f, 0.f, 0.f, 0.f};
        #pragma unroll 4
        for (int k = 0; k < HID; k += 4) {
            float4 xv = *reinterpret_cast<float4*>(&Xs[row][k]);
            #pragma unroll
            for (int i = 0; i < 4; i++) {
                float4 wv = *reinterpret_cast<float4*>(&W2s[cg + i][k]);
                s[i] += xv.x * wv.x + xv.y * wv.y + xv.z * wv.z + xv.w * wv.w;
            }
        }
        float dr = g_deg[m0 + row];
        float4 o = make_float4(dr * s[0], dr * s[1], dr * s[2], dr * s[3]);
        *reinterpret_cast<float4*>(&Y2out[(size_t)(m0 + row) * CLS + cg]) = o;
    }
}

// ---------------------------------------------------------------------------
// K5 (MMA): out[i][:] = log_softmax( d[i] * (A[i,:] @ Y2) )
// 32 rows/block (256 blocks), N=16, BK=64, cp.async double-buffered.
// 8 warps = 2 M-warps x 4 K-split warps; smem reduction + log-softmax epilogue.
// Fragment strides: As 68 (4g+t bijective mod 32), Bs 24 (t*24+g disjoint).
// ---------------------------------------------------------------------------
#define K5_M  32
#define K5_BK 64

__global__ __launch_bounds__(256, 2)
void k_out_mma(const float* __restrict__ A,
               const float* __restrict__ Y2,
               float* __restrict__ out)
{
    __shared__ uint32_t As[2][K5_M][68];
    __shared__ uint32_t Bs[2][K5_BK][24];
    __shared__ float    Rs[4][K5_M][20];

    const int m0 = blockIdx.x * K5_M;
    const int tid = threadIdx.x, lane = tid & 31, warp = tid >> 5;
    const int wm = (warp >> 2) * 16;      // 0 or 16
    const int wk = warp & 3;              // K-split 0..3
    const int g = lane >> 2, t = lane & 3;

    float acc[2][4] = {};

    const int a_row = tid >> 4, a_c4 = tid & 15;   // A: 32x64 = 512 chunks, 2/thread
    const int b_row = tid >> 2, b_c4 = tid & 3;    // B: 64x16 = 256 chunks, 1/thread

    auto issue = [&](int kt, int buf) {
        const float* asrc = A + (size_t)(m0 + a_row) * N_NODES + kt * K5_BK + a_c4 * 4;
        cp16(&As[buf][a_row][a_c4 * 4], asrc);
        cp16(&As[buf][a_row + 16][a_c4 * 4], asrc + (size_t)16 * N_NODES);
        cp16(&Bs[buf][b_row][b_c4 * 4],
             Y2 + (size_t)(kt * K5_BK + b_row) * CLS + b_c4 * 4);
    };

    const int nk = N_NODES / K5_BK;   // 128
    issue(0, 0);
    cp_commit();

    for (int kt = 0; kt < nk; kt++) {
        const int buf = kt & 1;
        if (kt + 1 < nk) {
            issue(kt + 1, buf ^ 1);
            cp_commit();
            cp_wait<1>();
        } else {
            cp_wait<0>();
        }
        __syncthreads();

        #pragma unroll
        for (int kk = 0; kk < 2; kk++) {
            const int ks = wk * 16 + kk * 8;
            uint32_t af[4], bf[2][2];
            const int r = wm + g;
            af[0] = As[buf][r][ks + t];
            af[1] = As[buf][r + 8][ks + t];
            af[2] = As[buf][r][ks + t + 4];
            af[3] = As[buf][r + 8][ks + t + 4];
            #pragma unroll
            for (int ni = 0; ni < 2; ni++) {
                int c = ni * 8 + g;
                bf[ni][0] = Bs[buf][ks + t][c];
                bf[ni][1] = Bs[buf][ks + t + 4][c];
            }
            mma_tf32(acc[0], af, bf[0]);
            mma_tf32(acc[1], af, bf[1]);
        }
        __syncthreads();
    }

    // partials -> smem
    {
        const int r = wm + g;
        #pragma unroll
        for (int ni = 0; ni < 2; ni++) {
            int c = ni * 8 + 2 * t;
            Rs[wk][r][c]     = acc[ni][0];
            Rs[wk][r][c + 1] = acc[ni][1];
            Rs[wk][r + 8][c]     = acc[ni][2];
            Rs[wk][r + 8][c + 1] = acc[ni][3];
        }
    }
    __syncthreads();

    // reduce K-splits + d-scale + log-softmax (128 threads: 32 rows x 4 quads)
    if (tid < 128) {
        const int row = tid >> 2, cq = tid & 3;
        float4 v = make_float4(0.f, 0.f, 0.f, 0.f);
        #pragma unroll
        for (int k = 0; k < 4; k++) {
            float4 p = *reinterpret_cast<float4*>(&Rs[k][row][cq * 4]);
            v.x += p.x; v.y += p.y; v.z += p.z; v.w += p.w;
        }
        float di = g_deg[m0 + row];
        v.x *= di; v.y *= di; v.z *= di; v.w *= di;

        float m = fmaxf(fmaxf(v.x, v.y), fmaxf(v.z, v.w));
        m = fmaxf(m, __shfl_xor_sync(0xffffffffu, m, 1));
        m = fmaxf(m, __shfl_xor_sync(0xffffffffu, m, 2));
        float s = expf(v.x - m) + expf(v.y - m) + expf(v.z - m) + expf(v.w - m);
        s += __shfl_xor_sync(0xffffffffu, s, 1);
        s += __shfl_xor_sync(0xffffffffu, s, 2);
        float ls = logf(s) + m;

        float4 o = make_float4(v.x - ls, v.y - ls, v.z - ls, v.w - ls);
        *reinterpret_cast<float4*>(&out[(size_t)(m0 + row) * CLS + cq * 4]) = o;
    }
}

// ---------------------------------------------------------------------------
// launch
// ---------------------------------------------------------------------------
extern "C" void kernel_launch(void* const* d_in, const int* in_sizes, int n_in,
                              void* d_out, int out_size) {
    const float* X  = (const float*)d_in[0];   // [8192, 512]
    const float* A  = (const float*)d_in[1];   // [8192, 8192]
    const float* W1 = (const float*)d_in[2];   // [256, 512]
    const float* W2 = (const float*)d_in[3];   // [16, 256]
    float* out = (float*)d_out;                // [8192, 16]

    float *pY1 = nullptr, *pY2 = nullptr;
    cudaGetSymbolAddress((void**)&pY1, g_Y1);
    cudaGetSymbolAddress((void**)&pY2, g_Y2);

    cudaFuncSetAttribute(k_layer1_fused,
                         cudaFuncAttributeMaxDynamicSharedMemorySize,
                         L1_SMEM_BYTES);

    // K1: degree scaling vector
    k_rowsum<<<N_NODES, 256>>>(A);

    // K2: Y1 = d ⊙ (X @ W1^T)
    k_gemm_xw1<<<dim3(N_NODES / 128, HID / 64), 256>>>(X, W1, pY1);

    // K3+K4 fused: Y2 = d ⊙ (relu(d ⊙ (A @ Y1)) @ W2^T)
    k_layer1_fused<<<N_NODES / 64, 256, L1_SMEM_BYTES>>>(A, pY1, W2, pY2);

    // K5 (MMA): out = log_softmax(d ⊙ (A @ Y2))
    k_out_mma<<<N_NODES / K5_M, 256>>>(A, pY2, out);
}